// round 14
// baseline (speedup 1.0000x reference)
#include <cuda_runtime.h>
#include <math.h>

// Problem constants
#define B_   2
#define C_   512
#define HW_  32768          // H*W = 128*256
#define K_   19
#define GC_  4              // channels per block (1 per warp)
#define NCT_ (C_/GC_)       // 128 channel tiles
#define NCHUNK_ 8
#define PXC_ (HW_/NCHUNK_)  // 4096 pixels per chunk
#define NIT_ (PXC_/128)     // 32 iterations per block
#define TOTALB_ (B_*NCT_*NCHUNK_)   // 2048 seg blocks
#define NTAILB_ 32                  // tail blocks (8 per (b,t))
#define NPAIR_  (K_*K_)             // 361
#define PPB_    46                  // ceil(361/8) pairs per tail block

// Scratch (no cudaMalloc allowed).
// d_cen: channel-major [bt][k][c]; zero at load, re-zeroed by the loss block.
__device__ float d_cen[B_*2*K_*C_];
__device__ float d_dots[B_*2*NPAIR_];
__device__ unsigned int d_ctr1, d_ctr2;

// One S/T float4 pair routed into per-warp float2 bins (bank == f(lane): conflict-free)
#define RMW_(sv, tv, lv)                                                        \
    do {                                                                        \
        float2 v_;                                                              \
        v_ = bin[(lv).x*32 + lane]; v_.x += (sv).x; v_.y += (tv).x; bin[(lv).x*32 + lane] = v_; \
        v_ = bin[(lv).y*32 + lane]; v_.x += (sv).y; v_.y += (tv).y; bin[(lv).y*32 + lane] = v_; \
        v_ = bin[(lv).z*32 + lane]; v_.x += (sv).z; v_.y += (tv).z; bin[(lv).z*32 + lane] = v_; \
        v_ = bin[(lv).w*32 + lane]; v_.x += (sv).w; v_.y += (tv).w; bin[(lv).w*32 + lane] = v_; \
    } while (0)

// ---------------------------------------------------------------------------
// Single fused kernel, roles by blockIdx.
// Blocks [0,2048): segment sums (R11 42us hot loop, untouched). Arrival uses
//   the sanctioned pattern: stores -> __syncthreads -> tid0-only
//   __threadfence + counter bump. (R13 regression cause: per-THREAD
//   __threadfence — 262k MEMBAR.GPU throttled the stream to 2.8TB/s.)
// Blocks [2048,2080): tail. Spin on ctr1 (only 32 slots occupied: deadlock-
//   free), each computes 1/8 of one (b,t) Gram from L2-hot channel-major
//   d_cen, arrives on ctr2; last arriver computes the loss, zeroes d_cen,
//   resets counters. Cosine is count-scale-invariant: raw sums suffice.
// ---------------------------------------------------------------------------
__global__ __launch_bounds__(128, 6) void fused_kernel(
    const float* __restrict__ S,
    const float* __restrict__ T,
    const int*   __restrict__ tgt,
    float*       __restrict__ out)
{
    __shared__ float2 bins[GC_][K_*32];   // 19.5 KB (seg path only)
    __shared__ float  outb[GC_][2][K_];
    __shared__ float  red[GC_];
    __shared__ int    slast;

    int tid  = threadIdx.x;
    int lane = tid & 31;
    int warp = tid >> 5;

    if (blockIdx.x < TOTALB_) {
        // ================= SEG PATH =================
        int blk   = blockIdx.x;               // b*1024 + chunk*128 + ct
        int ct    = blk & (NCT_ - 1);
        int chunk = (blk >> 7) & (NCHUNK_ - 1);
        int b     = blk >> 10;
        int c     = ct * GC_ + warp;

        const float4* Sp = (const float4*)(S + ((size_t)(b*C_ + c))*HW_ + chunk*PXC_);
        const float4* Tp = (const float4*)(T + ((size_t)(b*C_ + c))*HW_ + chunk*PXC_);
        const int4*   Lp = (const int4*)(tgt + (size_t)b*HW_ + chunk*PXC_);

        float2* bin = bins[warp];
        for (int i = lane; i < K_*32; i += 32) bin[i] = make_float2(0.f, 0.f);
        __syncwarp();

        // Depth-2 software pipeline.
        float4 s0 = __ldcs(Sp + lane);
        float4 t0 = __ldcs(Tp + lane);
        int4   l0 = __ldg (Lp + lane);
        float4 s1 = __ldcs(Sp + 32 + lane);
        float4 t1 = __ldcs(Tp + 32 + lane);
        int4   l1 = __ldg (Lp + 32 + lane);

#pragma unroll 2
        for (int it = 2; it < NIT_; ++it) {
            int idx = it*32 + lane;
            float4 s2 = __ldcs(Sp + idx);
            float4 t2 = __ldcs(Tp + idx);
            int4   l2 = __ldg (Lp + idx);
            RMW_(s0, t0, l0);
            s0 = s1; t0 = t1; l0 = l1;
            s1 = s2; t1 = t2; l1 = l2;
        }
        RMW_(s0, t0, l0);
        RMW_(s1, t1, l1);
        __syncwarp();

        // Reduce 32 lanes per class; shuffle tree.
#pragma unroll
        for (int k = 0; k < K_; ++k) {
            float2 v = bin[k*32 + lane];
#pragma unroll
            for (int off = 16; off; off >>= 1) {
                v.x += __shfl_down_sync(0xffffffff, v.x, off);
                v.y += __shfl_down_sync(0xffffffff, v.y, off);
            }
            if (lane == 0) { outb[warp][0][k] = v.x; outb[warp][1][k] = v.y; }
        }
        __syncwarp();

        // Channel-major accumulate: d_cen[((b*2+t)*K + k)*C + c].
        for (int i = lane; i < 2*K_; i += 32) {   // 38 outputs > 32 lanes: loop
            int t = i >= K_;
            int k = i - t*K_;
            atomicAdd(&d_cen[((size_t)(b*2 + t)*K_ + k)*C_ + c], outb[warp][t][k]);
        }

        // Arrival: tid0-only release fence (threadFenceReduction pattern).
        __syncthreads();
        if (tid == 0) { __threadfence(); atomicAdd(&d_ctr1, 1u); }
        return;
    }

    // ================= TAIL PATH =================
    int g    = blockIdx.x - TOTALB_;   // 0..31
    int bt   = g >> 3;                 // 0..3
    int part = g & 7;                  // 0..7

    if (tid == 0) {
        while (atomicAdd(&d_ctr1, 0u) < TOTALB_) __nanosleep(64);
        __threadfence();               // acquire
    }
    __syncthreads();

    // Gram slice: pairs [part*PPB_, min(361,(part+1)*PPB_)), warp-per-pair,
    // lanes coalesced over channels (L2-hot).
    const float* cen = d_cen + (size_t)bt*K_*C_;
    int p0 = part*PPB_;
    int p1 = min(NPAIR_, p0 + PPB_);
    for (int p = p0 + warp; p < p1; p += GC_) {
        int i = p / K_, j = p % K_;
        const float* ri = cen + (size_t)i*C_;
        const float* rj = cen + (size_t)j*C_;
        float acc = 0.f;
#pragma unroll
        for (int m = 0; m < C_/32; ++m)
            acc += ri[m*32 + lane] * rj[m*32 + lane];
#pragma unroll
        for (int off = 16; off; off >>= 1)
            acc += __shfl_down_sync(0xffffffff, acc, off);
        if (lane == 0) d_dots[(size_t)bt*NPAIR_ + p] = acc;
    }

    __syncthreads();
    if (tid == 0) {
        __threadfence();
        slast = ((int)atomicAdd(&d_ctr2, 1u) == NTAILB_ - 1);
    }
    __syncthreads();
    if (!slast) return;
    if (tid == 0) __threadfence();     // acquire all d_dots
    __syncthreads();

    // Loss over 722 (b,i,j) entries.
    float v = 0.f;
    for (int p = tid; p < B_*NPAIR_; p += 128) {
        int j = p % K_; int r = p / K_;
        int i = r % K_; int bb = r / K_;
        const float* dS = d_dots + (size_t)(bb*2 + 0)*NPAIR_;
        const float* dT = d_dots + (size_t)(bb*2 + 1)*NPAIR_;
        float nSi = fmaxf(sqrtf(dS[i*K_ + i]), 1e-8f);
        float nSj = fmaxf(sqrtf(dS[j*K_ + j]), 1e-8f);
        float pS  = dS[i*K_ + j] / (nSi * nSj);
        float nTi = fmaxf(sqrtf(dT[i*K_ + i]), 1e-8f);
        float nTj = fmaxf(sqrtf(dT[j*K_ + j]), 1e-8f);
        float pT  = dT[i*K_ + j] / (nTi * nTj);
        float df  = pS - pT;
        v += df * df;
    }
#pragma unroll
    for (int off = 16; off; off >>= 1)
        v += __shfl_down_sync(0xffffffff, v, off);
    if (lane == 0) red[warp] = v;

    // Zero d_cen for the next graph replay (all readers are done: ctr2 full).
    for (int i = tid; i < B_*2*K_*C_; i += 128)
        d_cen[i] = 0.f;

    __syncthreads();
    if (tid == 0) {
        out[0]  = (red[0] + red[1] + red[2] + red[3]) / (float)(B_*NPAIR_);
        d_ctr1 = 0;                    // reset for next graph replay
        d_ctr2 = 0;
    }
}

// ---------------------------------------------------------------------------
extern "C" void kernel_launch(void* const* d_in, const int* in_sizes, int n_in,
                              void* d_out, int out_size)
{
    const float* S   = (const float*)d_in[0];   // preds_S [2,512,128,256] f32
    const float* T   = (const float*)d_in[1];   // preds_T [2,512,128,256] f32
    const int*   tgt = (const int*)  d_in[2];   // target  [2,1,128,256] i32
    float* out = (float*)d_out;                 // scalar f32

    fused_kernel<<<TOTALB_ + NTAILB_, 128>>>(S, T, tgt, out);   // single launch
}

// round 15
// speedup vs baseline: 1.3417x; 1.3417x over previous
#include <cuda_runtime.h>
#include <math.h>

// Problem constants
#define B_   2
#define C_   512
#define HW_  32768          // H*W = 128*256
#define K_   19
#define GC_  4              // channels per block (1 per warp)
#define NCT_ (C_/GC_)       // 128 channel tiles
#define NCHUNK_ 8
#define PXC_ (HW_/NCHUNK_)  // 4096 pixels per chunk
#define NIT_ (PXC_/128)     // 32 iterations per block

// Scratch (no cudaMalloc allowed).
// d_cen zero at load; seg accumulates atomically; tail re-zeroes after reading.
__device__ float d_cen[B_*2*C_*K_];
__device__ float d_dots[B_*2*K_*K_];
__device__ unsigned int d_ctr;

// One S/T float4 pair routed into per-warp float2 bins (bank == f(lane): conflict-free)
#define RMW_(sv, tv, lv)                                                        \
    do {                                                                        \
        float2 v_;                                                              \
        v_ = bin[(lv).x*32 + lane]; v_.x += (sv).x; v_.y += (tv).x; bin[(lv).x*32 + lane] = v_; \
        v_ = bin[(lv).y*32 + lane]; v_.x += (sv).y; v_.y += (tv).y; bin[(lv).y*32 + lane] = v_; \
        v_ = bin[(lv).z*32 + lane]; v_.x += (sv).z; v_.y += (tv).z; bin[(lv).z*32 + lane] = v_; \
        v_ = bin[(lv).w*32 + lane]; v_.x += (sv).w; v_.y += (tv).w; bin[(lv).w*32 + lane] = v_; \
    } while (0)

// ---------------------------------------------------------------------------
// Kernel 1: segment sums (R11 config, measured ~42us: depth-2 pipeline,
// atomic accumulation into k-contiguous d_cen). Byte-identical to R11.
// ---------------------------------------------------------------------------
__global__ __launch_bounds__(128, 6) void seg_kernel(
    const float* __restrict__ S,
    const float* __restrict__ T,
    const int*   __restrict__ tgt)
{
    __shared__ float2 bins[GC_][K_*32];   // 4 warps x 19x32 float2 = 19.5 KB
    __shared__ float  outb[GC_][2][K_];

    int tid  = threadIdx.x;
    int lane = tid & 31;
    int warp = tid >> 5;

    int blk   = blockIdx.x;               // b*1024 + chunk*128 + ct
    int ct    = blk & (NCT_ - 1);
    int chunk = (blk >> 7) & (NCHUNK_ - 1);
    int b     = blk >> 10;
    int c     = ct * GC_ + warp;

    const float4* Sp = (const float4*)(S + ((size_t)(b*C_ + c))*HW_ + chunk*PXC_);
    const float4* Tp = (const float4*)(T + ((size_t)(b*C_ + c))*HW_ + chunk*PXC_);
    const int4*   Lp = (const int4*)(tgt + (size_t)b*HW_ + chunk*PXC_);

    float2* bin = bins[warp];
    for (int i = lane; i < K_*32; i += 32) bin[i] = make_float2(0.f, 0.f);
    __syncwarp();

    // Depth-2 software pipeline.
    float4 s0 = __ldcs(Sp + lane);
    float4 t0 = __ldcs(Tp + lane);
    int4   l0 = __ldg (Lp + lane);
    float4 s1 = __ldcs(Sp + 32 + lane);
    float4 t1 = __ldcs(Tp + 32 + lane);
    int4   l1 = __ldg (Lp + 32 + lane);

#pragma unroll 2
    for (int it = 2; it < NIT_; ++it) {
        int idx = it*32 + lane;
        float4 s2 = __ldcs(Sp + idx);
        float4 t2 = __ldcs(Tp + idx);
        int4   l2 = __ldg (Lp + idx);
        RMW_(s0, t0, l0);
        s0 = s1; t0 = t1; l0 = l1;
        s1 = s2; t1 = t2; l1 = l2;
    }
    RMW_(s0, t0, l0);
    RMW_(s1, t1, l1);
    __syncwarp();

    // Reduce 32 lanes per class; shuffle tree.
#pragma unroll
    for (int k = 0; k < K_; ++k) {
        float2 v = bin[k*32 + lane];
#pragma unroll
        for (int off = 16; off; off >>= 1) {
            v.x += __shfl_down_sync(0xffffffff, v.x, off);
            v.y += __shfl_down_sync(0xffffffff, v.y, off);
        }
        if (lane == 0) { outb[warp][0][k] = v.x; outb[warp][1][k] = v.y; }
    }
    __syncwarp();

    // Accumulate straight into d_cen[(b*2+t)*C*K + c*K + k].
    for (int i = lane; i < 2*K_; i += 32) {   // 38 outputs > 32 lanes: loop
        int t = i >= K_;
        int k = i - t*K_;
        atomicAdd(&d_cen[((size_t)(b*2 + t)*C_ + c)*K_ + k], outb[warp][t][k]);
    }
}

// ---------------------------------------------------------------------------
// Kernel 2: gram+loss (R11 body), launched with PDL so its 4 blocks are
// resident BEFORE seg finishes; cudaGridDependencySynchronize() waits in-HW
// for seg grid completion + memory flush, replacing the ~20us launch/ramp
// cost of a dependent small kernel.
// ---------------------------------------------------------------------------
__global__ __launch_bounds__(1024) void gram_loss_kernel(float* __restrict__ out)
{
    __shared__ float cen[C_*K_];   // 38.9 KB
    __shared__ float red[32];
    __shared__ int   slast;

    // Wait for seg_kernel's grid (PDL dependency barrier).
    cudaGridDependencySynchronize();

    int bt   = blockIdx.x;         // b*2 + t
    int tid  = threadIdx.x;
    int lane = tid & 31;
    int warp = tid >> 5;

    for (int i = tid; i < C_*K_; i += 1024) {
        size_t g = (size_t)bt*C_*K_ + i;
        cen[i] = d_cen[g];
        d_cen[g] = 0.f;            // reset accumulator for next graph replay
    }
    __syncthreads();

    // Gram: warp per (i,j) pair; lanes over channels (stride 19: conflict-free).
    for (int p = warp; p < K_*K_; p += 32) {
        int i = p / K_, j = p % K_;
        float acc = 0.f;
#pragma unroll
        for (int c = lane; c < C_; c += 32)
            acc += cen[c*K_ + i] * cen[c*K_ + j];
#pragma unroll
        for (int off = 16; off; off >>= 1)
            acc += __shfl_down_sync(0xffffffff, acc, off);
        if (lane == 0) d_dots[(size_t)bt*K_*K_ + p] = acc;
    }

    __threadfence();
    __syncthreads();
    if (tid == 0) {
        unsigned r = atomicAdd(&d_ctr, 1u);
        slast = (r == B_*2 - 1);
    }
    __syncthreads();
    if (!slast) return;
    __threadfence();

    // Loss over 722 (b,i,j) entries.
    float v = 0.f;
    if (tid < B_*K_*K_) {
        int j = tid % K_; int r = tid / K_;
        int i = r % K_;   int bb = r / K_;
        const float* dS = d_dots + (size_t)(bb*2 + 0)*K_*K_;
        const float* dT = d_dots + (size_t)(bb*2 + 1)*K_*K_;
        float nSi = fmaxf(sqrtf(dS[i*K_ + i]), 1e-8f);
        float nSj = fmaxf(sqrtf(dS[j*K_ + j]), 1e-8f);
        float pS  = dS[i*K_ + j] / (nSi * nSj);
        float nTi = fmaxf(sqrtf(dT[i*K_ + i]), 1e-8f);
        float nTj = fmaxf(sqrtf(dT[j*K_ + j]), 1e-8f);
        float pT  = dT[i*K_ + j] / (nTi * nTj);
        float df  = pS - pT;
        v = df * df;
    }
#pragma unroll
    for (int off = 16; off; off >>= 1)
        v += __shfl_down_sync(0xffffffff, v, off);
    if (lane == 0) red[warp] = v;
    __syncthreads();
    if (warp == 0) {
        float s = red[lane];
#pragma unroll
        for (int off = 16; off; off >>= 1)
            s += __shfl_down_sync(0xffffffff, s, off);
        if (lane == 0) {
            out[0] = s / (float)(B_*K_*K_);
            d_ctr  = 0;   // reset for next call
        }
    }
}

// ---------------------------------------------------------------------------
extern "C" void kernel_launch(void* const* d_in, const int* in_sizes, int n_in,
                              void* d_out, int out_size)
{
    const float* S   = (const float*)d_in[0];   // preds_S [2,512,128,256] f32
    const float* T   = (const float*)d_in[1];   // preds_T [2,512,128,256] f32
    const int*   tgt = (const int*)  d_in[2];   // target  [2,1,128,256] i32
    float* out = (float*)d_out;                 // scalar f32

    seg_kernel<<<B_*NCT_*NCHUNK_, 128>>>(S, T, tgt);   // 2048 blocks

    // PDL launch: tail scheduled concurrently, gated in-kernel by
    // cudaGridDependencySynchronize(). Same stream (legacy default) as <<<>>>.
    cudaLaunchConfig_t cfg = {};
    cfg.gridDim          = dim3(B_*2);
    cfg.blockDim         = dim3(1024);
    cfg.dynamicSmemBytes = 0;
    cfg.stream           = (cudaStream_t)0;
    cudaLaunchAttribute attrs[1];
    attrs[0].id = cudaLaunchAttributeProgrammaticStreamSerialization;
    attrs[0].val.programmaticStreamSerializationAllowed = 1;
    cfg.attrs    = attrs;
    cfg.numAttrs = 1;
    float* outf = (float*)d_out;
    cudaLaunchKernelEx(&cfg, gram_loss_kernel, outf);
}

// round 16
// speedup vs baseline: 1.5344x; 1.1436x over previous
#include <cuda_runtime.h>
#include <math.h>

// Problem constants
#define B_   2
#define C_   512
#define HW_  32768          // H*W = 128*256
#define K_   19
#define GC_  4              // channels per block (1 per warp)
#define NCT_ (C_/GC_)       // 128 channel tiles
#define NCHUNK_ 8
#define PXC_ (HW_/NCHUNK_)  // 4096 pixels per chunk
#define NIT_ (PXC_/128)     // 32 iterations per block
#define NPAIR_ (K_*K_)      // 361
#define NW_    (B_*2*NPAIR_)        // 1444 gram warps
#define GRAMB_ ((NW_ + 7)/8)        // 181 blocks of 8 warps

// Scratch (no cudaMalloc allowed).
// d_cen zero at load; seg accumulates atomically; loss_kernel re-zeroes it.
__device__ float d_cen[B_*2*C_*K_];
__device__ float d_dots[B_*2*NPAIR_];

// One S/T float4 pair routed into per-warp float2 bins (bank == f(lane): conflict-free)
#define RMW_(sv, tv, lv)                                                        \
    do {                                                                        \
        float2 v_;                                                              \
        v_ = bin[(lv).x*32 + lane]; v_.x += (sv).x; v_.y += (tv).x; bin[(lv).x*32 + lane] = v_; \
        v_ = bin[(lv).y*32 + lane]; v_.x += (sv).y; v_.y += (tv).y; bin[(lv).y*32 + lane] = v_; \
        v_ = bin[(lv).z*32 + lane]; v_.x += (sv).z; v_.y += (tv).z; bin[(lv).z*32 + lane] = v_; \
        v_ = bin[(lv).w*32 + lane]; v_.x += (sv).w; v_.y += (tv).w; bin[(lv).w*32 + lane] = v_; \
    } while (0)

// ---------------------------------------------------------------------------
// Kernel 1: segment sums (R11 config, measured ~42us: depth-2 pipeline,
// atomic accumulation into k-contiguous d_cen). Byte-identical to R11.
// ---------------------------------------------------------------------------
__global__ __launch_bounds__(128, 6) void seg_kernel(
    const float* __restrict__ S,
    const float* __restrict__ T,
    const int*   __restrict__ tgt)
{
    __shared__ float2 bins[GC_][K_*32];   // 4 warps x 19x32 float2 = 19.5 KB
    __shared__ float  outb[GC_][2][K_];

    int tid  = threadIdx.x;
    int lane = tid & 31;
    int warp = tid >> 5;

    int blk   = blockIdx.x;               // b*1024 + chunk*128 + ct
    int ct    = blk & (NCT_ - 1);
    int chunk = (blk >> 7) & (NCHUNK_ - 1);
    int b     = blk >> 10;
    int c     = ct * GC_ + warp;

    const float4* Sp = (const float4*)(S + ((size_t)(b*C_ + c))*HW_ + chunk*PXC_);
    const float4* Tp = (const float4*)(T + ((size_t)(b*C_ + c))*HW_ + chunk*PXC_);
    const int4*   Lp = (const int4*)(tgt + (size_t)b*HW_ + chunk*PXC_);

    float2* bin = bins[warp];
    for (int i = lane; i < K_*32; i += 32) bin[i] = make_float2(0.f, 0.f);
    __syncwarp();

    // Depth-2 software pipeline.
    float4 s0 = __ldcs(Sp + lane);
    float4 t0 = __ldcs(Tp + lane);
    int4   l0 = __ldg (Lp + lane);
    float4 s1 = __ldcs(Sp + 32 + lane);
    float4 t1 = __ldcs(Tp + 32 + lane);
    int4   l1 = __ldg (Lp + 32 + lane);

#pragma unroll 2
    for (int it = 2; it < NIT_; ++it) {
        int idx = it*32 + lane;
        float4 s2 = __ldcs(Sp + idx);
        float4 t2 = __ldcs(Tp + idx);
        int4   l2 = __ldg (Lp + idx);
        RMW_(s0, t0, l0);
        s0 = s1; t0 = t1; l0 = l1;
        s1 = s2; t1 = t2; l1 = l2;
    }
    RMW_(s0, t0, l0);
    RMW_(s1, t1, l1);
    __syncwarp();

    // Reduce 32 lanes per class; shuffle tree.
#pragma unroll
    for (int k = 0; k < K_; ++k) {
        float2 v = bin[k*32 + lane];
#pragma unroll
        for (int off = 16; off; off >>= 1) {
            v.x += __shfl_down_sync(0xffffffff, v.x, off);
            v.y += __shfl_down_sync(0xffffffff, v.y, off);
        }
        if (lane == 0) { outb[warp][0][k] = v.x; outb[warp][1][k] = v.y; }
    }
    __syncwarp();

    // Accumulate straight into d_cen[(b*2+t)*C*K + c*K + k].
    for (int i = lane; i < 2*K_; i += 32) {   // 38 outputs > 32 lanes: loop
        int t = i >= K_;
        int k = i - t*K_;
        atomicAdd(&d_cen[((size_t)(b*2 + t)*C_ + c)*K_ + k], outb[warp][t][k]);
    }
}

// ---------------------------------------------------------------------------
// Kernel 2: Gram, warp-per-(bt,i,j) across 181 blocks — every SM gets work.
// Reads d_cen straight through L1/L2 (152KB region, each line reused ~19x).
// No smem staging, no counters, no fences. Cosine is count-scale-invariant,
// so raw class sums suffice.
// ---------------------------------------------------------------------------
__global__ __launch_bounds__(256) void gram_kernel()
{
    int gw   = (blockIdx.x*256 + threadIdx.x) >> 5;   // global warp id
    int lane = threadIdx.x & 31;
    if (gw >= NW_) return;

    int bt = gw / NPAIR_;
    int p  = gw - bt*NPAIR_;
    int i  = p / K_, j = p % K_;

    const float* cen = d_cen + (size_t)bt*C_*K_;
    float acc = 0.f;
#pragma unroll
    for (int m = 0; m < C_/32; ++m) {
        int c = m*32 + lane;
        acc += __ldg(cen + c*K_ + i) * __ldg(cen + c*K_ + j);
    }
#pragma unroll
    for (int off = 16; off; off >>= 1)
        acc += __shfl_down_sync(0xffffffff, acc, off);
    if (lane == 0) d_dots[(size_t)bt*NPAIR_ + p] = acc;
}

// ---------------------------------------------------------------------------
// Kernel 3: loss over 722 (b,i,j) entries + re-zero d_cen for the next
// graph replay. Launch-boundary ordering: no fences/atomics needed.
// ---------------------------------------------------------------------------
__global__ __launch_bounds__(1024) void loss_kernel(float* __restrict__ out)
{
    __shared__ float red[32];
    int tid  = threadIdx.x;
    int lane = tid & 31;
    int warp = tid >> 5;

    float v = 0.f;
    if (tid < B_*NPAIR_) {
        int j = tid % K_; int r = tid / K_;
        int i = r % K_;   int bb = r / K_;
        const float* dS = d_dots + (size_t)(bb*2 + 0)*NPAIR_;
        const float* dT = d_dots + (size_t)(bb*2 + 1)*NPAIR_;
        float nSi = fmaxf(sqrtf(dS[i*K_ + i]), 1e-8f);
        float nSj = fmaxf(sqrtf(dS[j*K_ + j]), 1e-8f);
        float pS  = dS[i*K_ + j] / (nSi * nSj);
        float nTi = fmaxf(sqrtf(dT[i*K_ + i]), 1e-8f);
        float nTj = fmaxf(sqrtf(dT[j*K_ + j]), 1e-8f);
        float pT  = dT[i*K_ + j] / (nTi * nTj);
        float df  = pS - pT;
        v = df * df;
    }

    // Re-zero accumulator (gram_kernel is done: launch ordering).
    for (int idx = tid; idx < B_*2*C_*K_; idx += 1024)
        d_cen[idx] = 0.f;

#pragma unroll
    for (int off = 16; off; off >>= 1)
        v += __shfl_down_sync(0xffffffff, v, off);
    if (lane == 0) red[warp] = v;
    __syncthreads();
    if (warp == 0) {
        float s = red[lane];
#pragma unroll
        for (int off = 16; off; off >>= 1)
            s += __shfl_down_sync(0xffffffff, s, off);
        if (lane == 0) out[0] = s / (float)(B_*NPAIR_);
    }
}

// ---------------------------------------------------------------------------
extern "C" void kernel_launch(void* const* d_in, const int* in_sizes, int n_in,
                              void* d_out, int out_size)
{
    const float* S   = (const float*)d_in[0];   // preds_S [2,512,128,256] f32
    const float* T   = (const float*)d_in[1];   // preds_T [2,512,128,256] f32
    const int*   tgt = (const int*)  d_in[2];   // target  [2,1,128,256] i32
    float* out = (float*)d_out;                 // scalar f32

    seg_kernel<<<B_*NCT_*NCHUNK_, 128>>>(S, T, tgt);   // 2048 blocks
    gram_kernel<<<GRAMB_, 256>>>();                    // 181 blocks
    loss_kernel<<<1, 1024>>>(out);                     // 1 block
}